// round 13
// baseline (speedup 1.0000x reference)
#include <cuda_runtime.h>
#include <cuda_fp16.h>
#include <cstdint>

#define NN 100000
#define NE 1600000
#define D  128
#define SCAN_BLOCKS 98   // ceil(NN / 1024)

// ---------------- scratch (device globals — no allocation allowed) ----------
__device__ __align__(16) int    g_cursor[NN];
__device__ __align__(16) int    g_rowptr[NN + 1];
__device__ __align__(16) int    g_blocksum[SCAN_BLOCKS];
__device__ __align__(16) int    g_col[NE];
__device__ __align__(16) __half g_hh  [(size_t)NN * D];   // fp16 node features (layer input)
__device__ __align__(16) __half g_aggh[(size_t)NN * D];   // fp16 aggregated features
// fragment-major fp16 weights: per layer 16 ksteps x 16 ntiles x 32 lanes x uint2
__device__ __align__(16) uint2  g_wtf [3 * 8192];

// fp16 tensor-core mma, fp32 accumulate (baseline PTX, works on compute_103)
__device__ __forceinline__ void mma_f16(float* c, const uint32_t* a,
                                        uint32_t b0, uint32_t b1) {
    asm volatile(
        "mma.sync.aligned.m16n8k16.row.col.f32.f16.f16.f32 "
        "{%0,%1,%2,%3}, {%4,%5,%6,%7}, {%8,%9}, {%0,%1,%2,%3};"
        : "+f"(c[0]), "+f"(c[1]), "+f"(c[2]), "+f"(c[3])
        : "r"(a[0]), "r"(a[1]), "r"(a[2]), "r"(a[3]), "r"(b0), "r"(b1));
}

__device__ __forceinline__ void ldmatrix_x4(uint32_t* a, uint32_t addr) {
    asm volatile("ldmatrix.sync.aligned.m8n8.x4.shared.b16 {%0,%1,%2,%3}, [%4];"
                 : "=r"(a[0]), "=r"(a[1]), "=r"(a[2]), "=r"(a[3]) : "r"(addr));
}

__device__ __forceinline__ void cp_async16(uint32_t dst, const void* src, int szbytes) {
    asm volatile("cp.async.cg.shared.global [%0], [%1], 16, %2;"
                 :: "r"(dst), "l"(src), "r"(szbytes) : "memory");
}
__device__ __forceinline__ uint32_t smem_u32(const void* p) {
    uint32_t a;
    asm("{ .reg .u64 t; cvta.to.shared.u64 t, %1; cvt.u32.u64 %0, t; }" : "=r"(a) : "l"(p));
    return a;
}

// ---------------- x -> fp16 copy (also zeroes the fill cursor) ---------------
__global__ void cvt_x_kernel(const float* __restrict__ x) {
    int i = blockIdx.x * blockDim.x + threadIdx.x;   // 3.2M threads
    if (i < NN) g_cursor[i] = 0;                     // covers 100K cursor slots
    if (i >= NN * D / 4) return;
    float4 v = ((const float4*)x)[i];
    __half2 h0 = __floats2half2_rn(v.x, v.y);
    __half2 h1 = __floats2half2_rn(v.z, v.w);
    ((uint2*)g_hh)[i] = make_uint2(*(uint32_t*)&h0, *(uint32_t*)&h1);
}

// ---------------- CSR build --------------------------------------------------
__global__ void hist_kernel(const int* __restrict__ ei) {
    int e = blockIdx.x * blockDim.x + threadIdx.x;
    if (e < NE) {
        int dst = ei[NE + e];
        if ((unsigned)dst < NN) atomicAdd(&g_cursor[dst], 1);
    }
}

__global__ void scan1_kernel() {
    const int tid  = threadIdx.x;
    const int lane = tid & 31;
    const int warp = tid >> 5;
    const int i    = blockIdx.x * 1024 + tid;
    int v = (i < NN) ? g_cursor[i] : 0;
    int x = v;
    #pragma unroll
    for (int off = 1; off < 32; off <<= 1) {
        int t = __shfl_up_sync(0xFFFFFFFFu, x, off);
        if (lane >= off) x += t;
    }
    __shared__ int wsum[32];
    if (lane == 31) wsum[warp] = x;
    __syncthreads();
    if (warp == 0) {
        int y = wsum[lane];
        #pragma unroll
        for (int off = 1; off < 32; off <<= 1) {
            int t = __shfl_up_sync(0xFFFFFFFFu, y, off);
            if (lane >= off) y += t;
        }
        wsum[lane] = y;
    }
    __syncthreads();
    int blockExcl = (warp > 0) ? wsum[warp - 1] : 0;
    if (i < NN) g_rowptr[i] = blockExcl + x - v;   // block-local exclusive
    if (tid == 1023) g_blocksum[blockIdx.x] = blockExcl + x;
}

// merged scan2+scan3: every block redundantly scans the 98 block sums in smem,
// then applies its own exclusive offset; also initializes the fill cursor.
__global__ void scan23_kernel() {
    __shared__ int s[128];
    int tid = threadIdx.x;
    if (tid < 128) s[tid] = (tid < SCAN_BLOCKS) ? g_blocksum[tid] : 0;
    __syncthreads();
    #pragma unroll
    for (int off = 1; off < 128; off <<= 1) {
        int t = 0;
        if (tid < 128 && tid >= off) t = s[tid - off];
        __syncthreads();
        if (tid < 128) s[tid] += t;
        __syncthreads();
    }
    int excl = (blockIdx.x > 0) ? s[blockIdx.x - 1] : 0;
    int i = blockIdx.x * 1024 + tid;
    if (i < NN) {
        int v = g_rowptr[i] + excl;
        g_rowptr[i] = v;
        g_cursor[i] = v;
    }
    if (blockIdx.x == SCAN_BLOCKS - 1 && tid == 0)
        g_rowptr[NN] = s[SCAN_BLOCKS - 1];
}

__global__ void fill_kernel(const int* __restrict__ ei) {
    int e = blockIdx.x * blockDim.x + threadIdx.x;
    if (e < NE) {
        int src = ei[e];
        int dst = ei[NE + e];
        if ((unsigned)dst < NN && (unsigned)src < NN) {
            int pos = atomicAdd(&g_cursor[dst], 1);
            g_col[pos] = src;
        }
    }
}

// ---------------- weight prep: fragment-major fp16 ---------------------------
__global__ void prep_wt_kernel(const float* __restrict__ wr1, const float* __restrict__ wo1,
                               const float* __restrict__ wr2, const float* __restrict__ wo2,
                               const float* __restrict__ wr3, const float* __restrict__ wo3) {
    int i = blockIdx.x * blockDim.x + threadIdx.x;   // over 49152 half2 slots
    if (i >= 3 * 16384) return;
    int j    = i & 1;
    int lane = (i >> 1) & 31;
    int nt   = (i >> 6) & 15;
    int ksg  = (i >> 10) & 15;
    int l    = i >> 14;
    int n = nt * 8 + (lane >> 2);
    int k = ksg * 16 + (lane & 3) * 2 + j * 8;
    const float* wr = (l == 0) ? wr1 : (l == 1 ? wr2 : wr3);
    const float* wo = (l == 0) ? wo1 : (l == 1 ? wo2 : wo3);
    float v0, v1;
    if (k < 128) { v0 = wr[k * 128 + n];        v1 = wr[(k + 1) * 128 + n]; }
    else         { v0 = wo[(k - 128) * 128 + n]; v1 = wo[(k - 127) * 128 + n]; }
    __half2 h = __floats2half2_rn(v0, v1);
    ((uint32_t*)g_wtf)[i] = *(uint32_t*)&h;
}

// ---------------- aggregation: warp/node, masked 8-edge batches --------------
// All batches (incl. the last partial one) issue 8 independent loads; the last
// batch clamps indices to end-1 and predicates accumulation on edge validity.
__global__ void agg_kernel() {
    int gw   = (blockIdx.x * blockDim.x + threadIdx.x) >> 5;
    int lane = threadIdx.x & 31;
    if (gw >= NN) return;
    int beg = g_rowptr[gw];
    int end = g_rowptr[gw + 1];
    const uint2* hv = (const uint2*)g_hh;   // 32 uint2 per row
    float4 acc = make_float4(0.f, 0.f, 0.f, 0.f);
    for (int j = beg; j < end; j += 8) {
        int idx = j + (lane & 7);
        int myc = g_col[idx < end ? idx : end - 1];
        int s[8];
        #pragma unroll
        for (int e = 0; e < 8; e++) s[e] = __shfl_sync(0xFFFFFFFFu, myc, e);
        uint2 u[8];
        #pragma unroll
        for (int e = 0; e < 8; e++) u[e] = hv[(size_t)s[e] * 32 + lane];
        #pragma unroll
        for (int e = 0; e < 8; e++) {
            if (j + e < end) {
                float2 a = __half22float2(*(__half2*)&u[e].x);
                float2 b = __half22float2(*(__half2*)&u[e].y);
                acc.x += a.x; acc.y += a.y; acc.z += b.x; acc.w += b.y;
            }
        }
    }
    __half2 h0 = __floats2half2_rn(acc.x, acc.y);
    __half2 h1 = __floats2half2_rn(acc.z, acc.w);
    ((uint2*)g_aggh)[(size_t)gw * 32 + lane] = make_uint2(*(uint32_t*)&h0, *(uint32_t*)&h1);
}

// ---------------- fp16 GEMM: cp.async + ldmatrix + fragment-major B ----------
template <bool LAST>
__global__ void __launch_bounds__(256, 2)
gemm_mma_kernel(int layer, const float* __restrict__ bias, float* __restrict__ out)
{
    __shared__ __align__(16) uint8_t sA[2][128 * 128];

    const int tid  = threadIdx.x;
    const int lane = tid & 31;
    const int wid  = tid >> 5;
    const int wm   = wid & 3;     // 0..3  -> M
    const int wn   = wid >> 2;    // 0..1  -> N
    const int m0   = blockIdx.x * 128;
    const uint2* wtf = g_wtf + layer * 8192;
    const uint32_t sbase = smem_u32(sA);

    float acc[2][8][4];
    #pragma unroll
    for (int i = 0; i < 2; i++)
        #pragma unroll
        for (int j = 0; j < 8; j++)
            #pragma unroll
            for (int k = 0; k < 4; k++) acc[i][j][k] = 0.f;

    auto stage = [&](int c) {
        const __half* Asrc = (c < 2) ? g_aggh : g_hh;
        const uint8_t* base = (const uint8_t*)Asrc;
        const int cc = (c & 1) * 128;
        const uint32_t bufb = sbase + (uint32_t)(c & 1) * (128 * 128);
        #pragma unroll
        for (int it = 0; it < 4; it++) {
            int idx = it * 256 + tid;
            int r = idx >> 3, u = idx & 7;
            uint32_t dst = bufb + r * 128 + ((u ^ (r & 7)) * 16);
            const uint8_t* src = base + (size_t)(m0 + r) * 256 + cc + u * 16;
            int sz = (m0 + r < NN) ? 16 : 0;
            cp_async16(dst, src, sz);
        }
        asm volatile("cp.async.commit_group;" ::: "memory");
    };

    stage(0);

    #pragma unroll 1
    for (int c = 0; c < 4; c++) {
        if (c < 3) {
            stage(c + 1);
            asm volatile("cp.async.wait_group 1;" ::: "memory");
        } else {
            asm volatile("cp.async.wait_group 0;" ::: "memory");
        }
        __syncthreads();

        const uint32_t bufb = sbase + (uint32_t)(c & 1) * (128 * 128);
        #pragma unroll
        for (int ks = 0; ks < 4; ks++) {
            uint32_t a[2][4];
            #pragma unroll
            for (int mtl = 0; mtl < 2; mtl++) {
                int mt   = wm * 2 + mtl;
                int row  = mt * 16 + (lane & 15);
                int unit = 2 * ks + (lane >> 4);
                uint32_t addr = bufb + row * 128 + ((unit ^ (row & 7)) * 16);
                ldmatrix_x4(a[mtl], addr);
            }
            #pragma unroll
            for (int ntl = 0; ntl < 8; ntl++) {
                uint2 bv = wtf[(((c * 4 + ks) * 16) + wn * 8 + ntl) * 32 + lane];
                mma_f16(acc[0][ntl], a[0], bv.x, bv.y);
                mma_f16(acc[1][ntl], a[1], bv.x, bv.y);
            }
        }
        __syncthreads();
    }

    // ---- epilogue ----
    const int g   = lane >> 2;
    const int tig = lane & 3;
    #pragma unroll
    for (int mtl = 0; mtl < 2; mtl++) {
        #pragma unroll
        for (int h = 0; h < 2; h++) {
            int row = m0 + wm * 32 + mtl * 16 + h * 8 + g;
            if (row >= NN) continue;
            #pragma unroll
            for (int ntl = 0; ntl < 8; ntl++) {
                int col = wn * 64 + ntl * 8 + tig * 2;
                float ox = acc[mtl][ntl][h * 2 + 0] + __ldg(&bias[col + 0]);
                float oy = acc[mtl][ntl][h * 2 + 1] + __ldg(&bias[col + 1]);
                if (!LAST) {
                    ox = fmaxf(ox, 0.f); oy = fmaxf(oy, 0.f);
                    __half2 hh = __floats2half2_rn(ox, oy);
                    *(__half2*)&g_hh[(size_t)row * 128 + col] = hh;
                } else {
                    *(float2*)&out[(size_t)row * 128 + col] = make_float2(ox, oy);
                }
            }
        }
    }
}

// ---------------- launch ------------------------------------------------------
extern "C" void kernel_launch(void* const* d_in, const int* in_sizes, int n_in,
                              void* d_out, int out_size) {
    const float* x       = (const float*)d_in[0];
    const int*   ei      = (const int*)d_in[1];
    const float* w_rel1  = (const float*)d_in[2];
    const float* w_root1 = (const float*)d_in[3];
    const float* b1      = (const float*)d_in[4];
    const float* w_rel2  = (const float*)d_in[5];
    const float* w_root2 = (const float*)d_in[6];
    const float* b2      = (const float*)d_in[7];
    const float* w_rel3  = (const float*)d_in[8];
    const float* w_root3 = (const float*)d_in[9];
    const float* b3      = (const float*)d_in[10];
    float*       out     = (float*)d_out;

    const int EB = (NE + 255) / 256;
    const int AB = ((NN * 32) + 255) / 256;
    const int GB = (NN + 127) / 128;            // 782
    const int CB = (NN * D / 4 + 255) / 256;    // 12500

    cvt_x_kernel<<<CB, 256>>>(x);               // fp16 copy + cursor zero
    hist_kernel<<<EB, 256>>>(ei);
    scan1_kernel<<<SCAN_BLOCKS, 1024>>>();
    scan23_kernel<<<SCAN_BLOCKS, 1024>>>();
    fill_kernel<<<EB, 256>>>(ei);

    // layer 1
    agg_kernel<<<AB, 256>>>();
    prep_wt_kernel<<<192, 256>>>(w_rel1, w_root1, w_rel2, w_root2, w_rel3, w_root3);
    gemm_mma_kernel<false><<<GB, 256>>>(0, b1, nullptr);
    // layer 2
    agg_kernel<<<AB, 256>>>();
    gemm_mma_kernel<false><<<GB, 256>>>(1, b2, nullptr);
    // layer 3 (no relu) -> d_out
    agg_kernel<<<AB, 256>>>();
    gemm_mma_kernel<true><<<GB, 256>>>(2, b3, out);
}

// round 14
// speedup vs baseline: 1.0534x; 1.0534x over previous
#include <cuda_runtime.h>
#include <cuda_fp16.h>
#include <cstdint>

#define NN 100000
#define NE 1600000
#define D  128
#define SCAN_BLOCKS 98   // ceil(NN / 1024)

// ---------------- scratch (device globals — no allocation allowed) ----------
__device__ __align__(16) int    g_cursor[NN];
__device__ __align__(16) int    g_rowptr[NN + 1];
__device__ __align__(16) int    g_blocksum[SCAN_BLOCKS];
__device__ __align__(16) int    g_col[NE];
__device__ __align__(16) __half g_hh  [(size_t)NN * D];   // fp16 node features (layer input)
__device__ __align__(16) __half g_aggh[(size_t)NN * D];   // fp16 aggregated features
// fragment-major fp16 weights: per layer 16 ksteps x 16 ntiles x 32 lanes x uint2
__device__ __align__(16) uint2  g_wtf [3 * 8192];

// fp16 tensor-core mma, fp32 accumulate (baseline PTX, works on compute_103)
__device__ __forceinline__ void mma_f16(float* c, const uint32_t* a,
                                        uint32_t b0, uint32_t b1) {
    asm volatile(
        "mma.sync.aligned.m16n8k16.row.col.f32.f16.f16.f32 "
        "{%0,%1,%2,%3}, {%4,%5,%6,%7}, {%8,%9}, {%0,%1,%2,%3};"
        : "+f"(c[0]), "+f"(c[1]), "+f"(c[2]), "+f"(c[3])
        : "r"(a[0]), "r"(a[1]), "r"(a[2]), "r"(a[3]), "r"(b0), "r"(b1));
}

__device__ __forceinline__ void ldmatrix_x4(uint32_t* a, uint32_t addr) {
    asm volatile("ldmatrix.sync.aligned.m8n8.x4.shared.b16 {%0,%1,%2,%3}, [%4];"
                 : "=r"(a[0]), "=r"(a[1]), "=r"(a[2]), "=r"(a[3]) : "r"(addr));
}

__device__ __forceinline__ void cp_async16(uint32_t dst, const void* src, int szbytes) {
    asm volatile("cp.async.cg.shared.global [%0], [%1], 16, %2;"
                 :: "r"(dst), "l"(src), "r"(szbytes) : "memory");
}
__device__ __forceinline__ uint32_t smem_u32(const void* p) {
    uint32_t a;
    asm("{ .reg .u64 t; cvta.to.shared.u64 t, %1; cvt.u32.u64 %0, t; }" : "=r"(a) : "l"(p));
    return a;
}

// ---------------- x -> fp16 copy (also zeroes the fill cursor) ---------------
__global__ void cvt_x_kernel(const float* __restrict__ x) {
    int i = blockIdx.x * blockDim.x + threadIdx.x;   // 3.2M threads
    if (i < NN) g_cursor[i] = 0;                     // covers 100K cursor slots
    if (i >= NN * D / 4) return;
    float4 v = ((const float4*)x)[i];
    __half2 h0 = __floats2half2_rn(v.x, v.y);
    __half2 h1 = __floats2half2_rn(v.z, v.w);
    ((uint2*)g_hh)[i] = make_uint2(*(uint32_t*)&h0, *(uint32_t*)&h1);
}

// ---------------- CSR build --------------------------------------------------
__global__ void hist_kernel(const int* __restrict__ ei) {
    int e = blockIdx.x * blockDim.x + threadIdx.x;
    if (e < NE) {
        int dst = ei[NE + e];
        if ((unsigned)dst < NN) atomicAdd(&g_cursor[dst], 1);
    }
}

__global__ void scan1_kernel() {
    const int tid  = threadIdx.x;
    const int lane = tid & 31;
    const int warp = tid >> 5;
    const int i    = blockIdx.x * 1024 + tid;
    int v = (i < NN) ? g_cursor[i] : 0;
    int x = v;
    #pragma unroll
    for (int off = 1; off < 32; off <<= 1) {
        int t = __shfl_up_sync(0xFFFFFFFFu, x, off);
        if (lane >= off) x += t;
    }
    __shared__ int wsum[32];
    if (lane == 31) wsum[warp] = x;
    __syncthreads();
    if (warp == 0) {
        int y = wsum[lane];
        #pragma unroll
        for (int off = 1; off < 32; off <<= 1) {
            int t = __shfl_up_sync(0xFFFFFFFFu, y, off);
            if (lane >= off) y += t;
        }
        wsum[lane] = y;
    }
    __syncthreads();
    int blockExcl = (warp > 0) ? wsum[warp - 1] : 0;
    if (i < NN) g_rowptr[i] = blockExcl + x - v;   // block-local exclusive
    if (tid == 1023) g_blocksum[blockIdx.x] = blockExcl + x;
}

// merged scan2+scan3: every block redundantly scans the 98 block sums in smem,
// then applies its own exclusive offset; also initializes the fill cursor.
__global__ void scan23_kernel() {
    __shared__ int s[128];
    int tid = threadIdx.x;
    if (tid < 128) s[tid] = (tid < SCAN_BLOCKS) ? g_blocksum[tid] : 0;
    __syncthreads();
    #pragma unroll
    for (int off = 1; off < 128; off <<= 1) {
        int t = 0;
        if (tid < 128 && tid >= off) t = s[tid - off];
        __syncthreads();
        if (tid < 128) s[tid] += t;
        __syncthreads();
    }
    int excl = (blockIdx.x > 0) ? s[blockIdx.x - 1] : 0;
    int i = blockIdx.x * 1024 + tid;
    if (i < NN) {
        int v = g_rowptr[i] + excl;
        g_rowptr[i] = v;
        g_cursor[i] = v;
    }
    if (blockIdx.x == SCAN_BLOCKS - 1 && tid == 0)
        g_rowptr[NN] = s[SCAN_BLOCKS - 1];
}

__global__ void fill_kernel(const int* __restrict__ ei) {
    int e = blockIdx.x * blockDim.x + threadIdx.x;
    if (e < NE) {
        int src = ei[e];
        int dst = ei[NE + e];
        if ((unsigned)dst < NN && (unsigned)src < NN) {
            int pos = atomicAdd(&g_cursor[dst], 1);
            g_col[pos] = src;
        }
    }
}

// ---------------- weight prep: fragment-major fp16 ---------------------------
__global__ void prep_wt_kernel(const float* __restrict__ wr1, const float* __restrict__ wo1,
                               const float* __restrict__ wr2, const float* __restrict__ wo2,
                               const float* __restrict__ wr3, const float* __restrict__ wo3) {
    int i = blockIdx.x * blockDim.x + threadIdx.x;   // over 49152 half2 slots
    if (i >= 3 * 16384) return;
    int j    = i & 1;
    int lane = (i >> 1) & 31;
    int nt   = (i >> 6) & 15;
    int ksg  = (i >> 10) & 15;
    int l    = i >> 14;
    int n = nt * 8 + (lane >> 2);
    int k = ksg * 16 + (lane & 3) * 2 + j * 8;
    const float* wr = (l == 0) ? wr1 : (l == 1 ? wr2 : wr3);
    const float* wo = (l == 0) ? wo1 : (l == 1 ? wo2 : wo3);
    float v0, v1;
    if (k < 128) { v0 = wr[k * 128 + n];        v1 = wr[(k + 1) * 128 + n]; }
    else         { v0 = wo[(k - 128) * 128 + n]; v1 = wo[(k - 127) * 128 + n]; }
    __half2 h = __floats2half2_rn(v0, v1);
    ((uint32_t*)g_wtf)[i] = *(uint32_t*)&h;
}

// ---------------- aggregation: warp/node, 8-edge batches + col prefetch ------
// Identical to the best (R12) loop except the next batch's column indices are
// prefetched while the current batch's feature loads are in flight.
__global__ void agg_kernel() {
    int gw   = (blockIdx.x * blockDim.x + threadIdx.x) >> 5;
    int lane = threadIdx.x & 31;
    if (gw >= NN) return;
    int beg = g_rowptr[gw];
    int end = g_rowptr[gw + 1];
    const uint2* hv = (const uint2*)g_hh;   // 32 uint2 per row
    const int l8 = lane & 7;
    float4 acc = make_float4(0.f, 0.f, 0.f, 0.f);
    int j = beg;
    int myc = 0;
    if (j + 8 <= end) myc = g_col[j + l8];
    for (; j + 8 <= end; j += 8) {
        int cur = myc;
        if (j + 16 <= end) myc = g_col[j + 8 + l8];   // prefetch next batch
        int s[8];
        #pragma unroll
        for (int e = 0; e < 8; e++) s[e] = __shfl_sync(0xFFFFFFFFu, cur, e);
        uint2 u[8];
        #pragma unroll
        for (int e = 0; e < 8; e++) u[e] = hv[(size_t)s[e] * 32 + lane];
        #pragma unroll
        for (int e = 0; e < 8; e++) {
            float2 a = __half22float2(*(__half2*)&u[e].x);
            float2 b = __half22float2(*(__half2*)&u[e].y);
            acc.x += a.x; acc.y += a.y; acc.z += b.x; acc.w += b.y;
        }
    }
    if (j < end) {
        int rem = end - j;   // 1..7
        int c = (l8 < rem) ? g_col[j + l8] : 0;
        for (int e = 0; e < rem; e++) {
            int s = __shfl_sync(0xFFFFFFFFu, c, e);
            uint2 u = hv[(size_t)s * 32 + lane];
            float2 a = __half22float2(*(__half2*)&u.x);
            float2 b = __half22float2(*(__half2*)&u.y);
            acc.x += a.x; acc.y += a.y; acc.z += b.x; acc.w += b.y;
        }
    }
    __half2 h0 = __floats2half2_rn(acc.x, acc.y);
    __half2 h1 = __floats2half2_rn(acc.z, acc.w);
    ((uint2*)g_aggh)[(size_t)gw * 32 + lane] = make_uint2(*(uint32_t*)&h0, *(uint32_t*)&h1);
}

// ---------------- fp16 GEMM: cp.async + ldmatrix + fragment-major B ----------
template <bool LAST>
__global__ void __launch_bounds__(256, 2)
gemm_mma_kernel(int layer, const float* __restrict__ bias, float* __restrict__ out)
{
    __shared__ __align__(16) uint8_t sA[2][128 * 128];

    const int tid  = threadIdx.x;
    const int lane = tid & 31;
    const int wid  = tid >> 5;
    const int wm   = wid & 3;     // 0..3  -> M
    const int wn   = wid >> 2;    // 0..1  -> N
    const int m0   = blockIdx.x * 128;
    const uint2* wtf = g_wtf + layer * 8192;
    const uint32_t sbase = smem_u32(sA);

    float acc[2][8][4];
    #pragma unroll
    for (int i = 0; i < 2; i++)
        #pragma unroll
        for (int j = 0; j < 8; j++)
            #pragma unroll
            for (int k = 0; k < 4; k++) acc[i][j][k] = 0.f;

    auto stage = [&](int c) {
        const __half* Asrc = (c < 2) ? g_aggh : g_hh;
        const uint8_t* base = (const uint8_t*)Asrc;
        const int cc = (c & 1) * 128;
        const uint32_t bufb = sbase + (uint32_t)(c & 1) * (128 * 128);
        #pragma unroll
        for (int it = 0; it < 4; it++) {
            int idx = it * 256 + tid;
            int r = idx >> 3, u = idx & 7;
            uint32_t dst = bufb + r * 128 + ((u ^ (r & 7)) * 16);
            const uint8_t* src = base + (size_t)(m0 + r) * 256 + cc + u * 16;
            int sz = (m0 + r < NN) ? 16 : 0;
            cp_async16(dst, src, sz);
        }
        asm volatile("cp.async.commit_group;" ::: "memory");
    };

    stage(0);

    #pragma unroll 1
    for (int c = 0; c < 4; c++) {
        if (c < 3) {
            stage(c + 1);
            asm volatile("cp.async.wait_group 1;" ::: "memory");
        } else {
            asm volatile("cp.async.wait_group 0;" ::: "memory");
        }
        __syncthreads();

        const uint32_t bufb = sbase + (uint32_t)(c & 1) * (128 * 128);
        #pragma unroll
        for (int ks = 0; ks < 4; ks++) {
            uint32_t a[2][4];
            #pragma unroll
            for (int mtl = 0; mtl < 2; mtl++) {
                int mt   = wm * 2 + mtl;
                int row  = mt * 16 + (lane & 15);
                int unit = 2 * ks + (lane >> 4);
                uint32_t addr = bufb + row * 128 + ((unit ^ (row & 7)) * 16);
                ldmatrix_x4(a[mtl], addr);
            }
            #pragma unroll
            for (int ntl = 0; ntl < 8; ntl++) {
                uint2 bv = wtf[(((c * 4 + ks) * 16) + wn * 8 + ntl) * 32 + lane];
                mma_f16(acc[0][ntl], a[0], bv.x, bv.y);
                mma_f16(acc[1][ntl], a[1], bv.x, bv.y);
            }
        }
        __syncthreads();
    }

    // ---- epilogue ----
    const int g   = lane >> 2;
    const int tig = lane & 3;
    #pragma unroll
    for (int mtl = 0; mtl < 2; mtl++) {
        #pragma unroll
        for (int h = 0; h < 2; h++) {
            int row = m0 + wm * 32 + mtl * 16 + h * 8 + g;
            if (row >= NN) continue;
            #pragma unroll
            for (int ntl = 0; ntl < 8; ntl++) {
                int col = wn * 64 + ntl * 8 + tig * 2;
                float ox = acc[mtl][ntl][h * 2 + 0] + __ldg(&bias[col + 0]);
                float oy = acc[mtl][ntl][h * 2 + 1] + __ldg(&bias[col + 1]);
                if (!LAST) {
                    ox = fmaxf(ox, 0.f); oy = fmaxf(oy, 0.f);
                    __half2 hh = __floats2half2_rn(ox, oy);
                    *(__half2*)&g_hh[(size_t)row * 128 + col] = hh;
                } else {
                    *(float2*)&out[(size_t)row * 128 + col] = make_float2(ox, oy);
                }
            }
        }
    }
}

// ---------------- launch ------------------------------------------------------
extern "C" void kernel_launch(void* const* d_in, const int* in_sizes, int n_in,
                              void* d_out, int out_size) {
    const float* x       = (const float*)d_in[0];
    const int*   ei      = (const int*)d_in[1];
    const float* w_rel1  = (const float*)d_in[2];
    const float* w_root1 = (const float*)d_in[3];
    const float* b1      = (const float*)d_in[4];
    const float* w_rel2  = (const float*)d_in[5];
    const float* w_root2 = (const float*)d_in[6];
    const float* b2      = (const float*)d_in[7];
    const float* w_rel3  = (const float*)d_in[8];
    const float* w_root3 = (const float*)d_in[9];
    const float* b3      = (const float*)d_in[10];
    float*       out     = (float*)d_out;

    const int EB = (NE + 255) / 256;
    const int AB = ((NN * 32) + 255) / 256;
    const int GB = (NN + 127) / 128;            // 782
    const int CB = (NN * D / 4 + 255) / 256;    // 12500

    cvt_x_kernel<<<CB, 256>>>(x);               // fp16 copy + cursor zero
    hist_kernel<<<EB, 256>>>(ei);
    scan1_kernel<<<SCAN_BLOCKS, 1024>>>();
    scan23_kernel<<<SCAN_BLOCKS, 1024>>>();
    fill_kernel<<<EB, 256>>>(ei);

    // layer 1
    agg_kernel<<<AB, 256>>>();
    prep_wt_kernel<<<192, 256>>>(w_rel1, w_root1, w_rel2, w_root2, w_rel3, w_root3);
    gemm_mma_kernel<false><<<GB, 256>>>(0, b1, nullptr);
    // layer 2
    agg_kernel<<<AB, 256>>>();
    gemm_mma_kernel<false><<<GB, 256>>>(1, b2, nullptr);
    // layer 3 (no relu) -> d_out
    agg_kernel<<<AB, 256>>>();
    gemm_mma_kernel<true><<<GB, 256>>>(2, b3, out);
}

// round 15
// speedup vs baseline: 1.0721x; 1.0177x over previous
#include <cuda_runtime.h>
#include <cuda_fp16.h>
#include <cstdint>

#define NN 100000
#define NE 1600000
#define D  128
#define SCAN_BLOCKS 98   // ceil(NN / 1024)

// ---------------- scratch (device globals — no allocation allowed) ----------
__device__ __align__(16) int    g_cursor[NN];
__device__ __align__(16) int    g_rowptr[NN + 1];
__device__ __align__(16) int    g_blocksum[SCAN_BLOCKS];
__device__ __align__(16) int    g_col[NE];
__device__ __align__(16) __half g_hh  [(size_t)NN * D];   // fp16 node features (layer input)
__device__ __align__(16) __half g_aggh[(size_t)NN * D];   // fp16 aggregated features
// fragment-major fp16 weights, paired n-tiles:
// per layer: 16 ksteps x 8 ntile-pairs x 32 lanes x uint4 {b0e,b1e,b0o,b1o}
__device__ __align__(16) uint2  g_wtf [3 * 8192];

// fp16 tensor-core mma, fp32 accumulate (baseline PTX, works on compute_103)
__device__ __forceinline__ void mma_f16(float* c, const uint32_t* a,
                                        uint32_t b0, uint32_t b1) {
    asm volatile(
        "mma.sync.aligned.m16n8k16.row.col.f32.f16.f16.f32 "
        "{%0,%1,%2,%3}, {%4,%5,%6,%7}, {%8,%9}, {%0,%1,%2,%3};"
        : "+f"(c[0]), "+f"(c[1]), "+f"(c[2]), "+f"(c[3])
        : "r"(a[0]), "r"(a[1]), "r"(a[2]), "r"(a[3]), "r"(b0), "r"(b1));
}

__device__ __forceinline__ void ldmatrix_x4(uint32_t* a, uint32_t addr) {
    asm volatile("ldmatrix.sync.aligned.m8n8.x4.shared.b16 {%0,%1,%2,%3}, [%4];"
                 : "=r"(a[0]), "=r"(a[1]), "=r"(a[2]), "=r"(a[3]) : "r"(addr));
}

__device__ __forceinline__ void cp_async16(uint32_t dst, const void* src, int szbytes) {
    asm volatile("cp.async.cg.shared.global [%0], [%1], 16, %2;"
                 :: "r"(dst), "l"(src), "r"(szbytes) : "memory");
}
__device__ __forceinline__ uint32_t smem_u32(const void* p) {
    uint32_t a;
    asm("{ .reg .u64 t; cvta.to.shared.u64 t, %1; cvt.u32.u64 %0, t; }" : "=r"(a) : "l"(p));
    return a;
}

// ---------------- x -> fp16 copy (also zeroes the fill cursor) ---------------
__global__ void cvt_x_kernel(const float* __restrict__ x) {
    int i = blockIdx.x * blockDim.x + threadIdx.x;   // 3.2M threads
    if (i < NN) g_cursor[i] = 0;                     // covers 100K cursor slots
    if (i >= NN * D / 4) return;
    float4 v = ((const float4*)x)[i];
    __half2 h0 = __floats2half2_rn(v.x, v.y);
    __half2 h1 = __floats2half2_rn(v.z, v.w);
    ((uint2*)g_hh)[i] = make_uint2(*(uint32_t*)&h0, *(uint32_t*)&h1);
}

// ---------------- CSR build (int4-vectorized edge reads) ---------------------
__global__ void hist_kernel(const int* __restrict__ ei) {
    int e4 = blockIdx.x * blockDim.x + threadIdx.x;   // NE/4 quads
    if (e4 < NE / 4) {
        int4 d = ((const int4*)(ei + NE))[e4];
        if ((unsigned)d.x < NN) atomicAdd(&g_cursor[d.x], 1);
        if ((unsigned)d.y < NN) atomicAdd(&g_cursor[d.y], 1);
        if ((unsigned)d.z < NN) atomicAdd(&g_cursor[d.z], 1);
        if ((unsigned)d.w < NN) atomicAdd(&g_cursor[d.w], 1);
    }
}

__global__ void scan1_kernel() {
    const int tid  = threadIdx.x;
    const int lane = tid & 31;
    const int warp = tid >> 5;
    const int i    = blockIdx.x * 1024 + tid;
    int v = (i < NN) ? g_cursor[i] : 0;
    int x = v;
    #pragma unroll
    for (int off = 1; off < 32; off <<= 1) {
        int t = __shfl_up_sync(0xFFFFFFFFu, x, off);
        if (lane >= off) x += t;
    }
    __shared__ int wsum[32];
    if (lane == 31) wsum[warp] = x;
    __syncthreads();
    if (warp == 0) {
        int y = wsum[lane];
        #pragma unroll
        for (int off = 1; off < 32; off <<= 1) {
            int t = __shfl_up_sync(0xFFFFFFFFu, y, off);
            if (lane >= off) y += t;
        }
        wsum[lane] = y;
    }
    __syncthreads();
    int blockExcl = (warp > 0) ? wsum[warp - 1] : 0;
    if (i < NN) g_rowptr[i] = blockExcl + x - v;   // block-local exclusive
    if (tid == 1023) g_blocksum[blockIdx.x] = blockExcl + x;
}

// merged scan2+scan3: every block redundantly scans the 98 block sums in smem,
// then applies its own exclusive offset; also initializes the fill cursor.
__global__ void scan23_kernel() {
    __shared__ int s[128];
    int tid = threadIdx.x;
    if (tid < 128) s[tid] = (tid < SCAN_BLOCKS) ? g_blocksum[tid] : 0;
    __syncthreads();
    #pragma unroll
    for (int off = 1; off < 128; off <<= 1) {
        int t = 0;
        if (tid < 128 && tid >= off) t = s[tid - off];
        __syncthreads();
        if (tid < 128) s[tid] += t;
        __syncthreads();
    }
    int excl = (blockIdx.x > 0) ? s[blockIdx.x - 1] : 0;
    int i = blockIdx.x * 1024 + tid;
    if (i < NN) {
        int v = g_rowptr[i] + excl;
        g_rowptr[i] = v;
        g_cursor[i] = v;
    }
    if (blockIdx.x == SCAN_BLOCKS - 1 && tid == 0)
        g_rowptr[NN] = s[SCAN_BLOCKS - 1];
}

__global__ void fill_kernel(const int* __restrict__ ei) {
    int e4 = blockIdx.x * blockDim.x + threadIdx.x;   // NE/4 quads
    if (e4 < NE / 4) {
        int4 s = ((const int4*)ei)[e4];
        int4 d = ((const int4*)(ei + NE))[e4];
        if ((unsigned)d.x < NN && (unsigned)s.x < NN) g_col[atomicAdd(&g_cursor[d.x], 1)] = s.x;
        if ((unsigned)d.y < NN && (unsigned)s.y < NN) g_col[atomicAdd(&g_cursor[d.y], 1)] = s.y;
        if ((unsigned)d.z < NN && (unsigned)s.z < NN) g_col[atomicAdd(&g_cursor[d.z], 1)] = s.z;
        if ((unsigned)d.w < NN && (unsigned)s.w < NN) g_col[atomicAdd(&g_cursor[d.w], 1)] = s.w;
    }
}

// ---------------- weight prep: fragment-major fp16, paired n-tiles -----------
// u32 slot i: j2=i&3 (0:b0 even-ntl, 1:b1 even, 2:b0 odd, 3:b1 odd),
// lane=(i>>2)&31, nt2=(i>>7)&7, ksg=(i>>10)&15, layer=i>>14.
// ntl = nt2*2 + (j2>>1), j = j2&1; n = ntl*8 + lane/4; k = ksg*16 + (lane%4)*2 + j*8.
__global__ void prep_wt_kernel(const float* __restrict__ wr1, const float* __restrict__ wo1,
                               const float* __restrict__ wr2, const float* __restrict__ wo2,
                               const float* __restrict__ wr3, const float* __restrict__ wo3) {
    int i = blockIdx.x * blockDim.x + threadIdx.x;   // over 49152 u32 slots
    if (i >= 3 * 16384) return;
    int j2   = i & 3;
    int lane = (i >> 2) & 31;
    int nt2  = (i >> 7) & 7;
    int ksg  = (i >> 10) & 15;
    int l    = i >> 14;
    int ntl  = nt2 * 2 + (j2 >> 1);
    int j    = j2 & 1;
    int n = ntl * 8 + (lane >> 2);
    int k = ksg * 16 + (lane & 3) * 2 + j * 8;
    const float* wr = (l == 0) ? wr1 : (l == 1 ? wr2 : wr3);
    const float* wo = (l == 0) ? wo1 : (l == 1 ? wo2 : wo3);
    float v0, v1;
    if (k < 128) { v0 = wr[k * 128 + n];        v1 = wr[(k + 1) * 128 + n]; }
    else         { v0 = wo[(k - 128) * 128 + n]; v1 = wo[(k - 127) * 128 + n]; }
    __half2 h = __floats2half2_rn(v0, v1);
    ((uint32_t*)g_wtf)[i] = *(uint32_t*)&h;
}

// ---------------- aggregation: warp/node, 8-edge batches + col prefetch ------
__global__ void agg_kernel() {
    int gw   = (blockIdx.x * blockDim.x + threadIdx.x) >> 5;
    int lane = threadIdx.x & 31;
    if (gw >= NN) return;
    int beg = g_rowptr[gw];
    int end = g_rowptr[gw + 1];
    const uint2* hv = (const uint2*)g_hh;   // 32 uint2 per row
    const int l8 = lane & 7;
    float4 acc = make_float4(0.f, 0.f, 0.f, 0.f);
    int j = beg;
    int myc = 0;
    if (j + 8 <= end) myc = g_col[j + l8];
    for (; j + 8 <= end; j += 8) {
        int cur = myc;
        if (j + 16 <= end) myc = g_col[j + 8 + l8];   // prefetch next batch
        int s[8];
        #pragma unroll
        for (int e = 0; e < 8; e++) s[e] = __shfl_sync(0xFFFFFFFFu, cur, e);
        uint2 u[8];
        #pragma unroll
        for (int e = 0; e < 8; e++) u[e] = hv[(size_t)s[e] * 32 + lane];
        #pragma unroll
        for (int e = 0; e < 8; e++) {
            float2 a = __half22float2(*(__half2*)&u[e].x);
            float2 b = __half22float2(*(__half2*)&u[e].y);
            acc.x += a.x; acc.y += a.y; acc.z += b.x; acc.w += b.y;
        }
    }
    if (j < end) {
        int rem = end - j;   // 1..7
        int c = (l8 < rem) ? g_col[j + l8] : 0;
        for (int e = 0; e < rem; e++) {
            int s = __shfl_sync(0xFFFFFFFFu, c, e);
            uint2 u = hv[(size_t)s * 32 + lane];
            float2 a = __half22float2(*(__half2*)&u.x);
            float2 b = __half22float2(*(__half2*)&u.y);
            acc.x += a.x; acc.y += a.y; acc.z += b.x; acc.w += b.y;
        }
    }
    __half2 h0 = __floats2half2_rn(acc.x, acc.y);
    __half2 h1 = __floats2half2_rn(acc.z, acc.w);
    ((uint2*)g_aggh)[(size_t)gw * 32 + lane] = make_uint2(*(uint32_t*)&h0, *(uint32_t*)&h1);
}

// ---------------- fp16 GEMM: cp.async + ldmatrix + paired uint4 B loads ------
template <bool LAST>
__global__ void __launch_bounds__(256, 2)
gemm_mma_kernel(int layer, const float* __restrict__ bias, float* __restrict__ out)
{
    __shared__ __align__(16) uint8_t sA[2][128 * 128];

    const int tid  = threadIdx.x;
    const int lane = tid & 31;
    const int wid  = tid >> 5;
    const int wm   = wid & 3;     // 0..3  -> M
    const int wn   = wid >> 2;    // 0..1  -> N
    const int m0   = blockIdx.x * 128;
    const uint4* wtf4 = (const uint4*)(g_wtf + layer * 8192);
    const uint32_t sbase = smem_u32(sA);

    float acc[2][8][4];
    #pragma unroll
    for (int i = 0; i < 2; i++)
        #pragma unroll
        for (int j = 0; j < 8; j++)
            #pragma unroll
            for (int k = 0; k < 4; k++) acc[i][j][k] = 0.f;

    auto stage = [&](int c) {
        const __half* Asrc = (c < 2) ? g_aggh : g_hh;
        const uint8_t* base = (const uint8_t*)Asrc;
        const int cc = (c & 1) * 128;
        const uint32_t bufb = sbase + (uint32_t)(c & 1) * (128 * 128);
        #pragma unroll
        for (int it = 0; it < 4; it++) {
            int idx = it * 256 + tid;
            int r = idx >> 3, u = idx & 7;
            uint32_t dst = bufb + r * 128 + ((u ^ (r & 7)) * 16);
            const uint8_t* src = base + (size_t)(m0 + r) * 256 + cc + u * 16;
            int sz = (m0 + r < NN) ? 16 : 0;
            cp_async16(dst, src, sz);
        }
        asm volatile("cp.async.commit_group;" ::: "memory");
    };

    stage(0);

    #pragma unroll 1
    for (int c = 0; c < 4; c++) {
        if (c < 3) {
            stage(c + 1);
            asm volatile("cp.async.wait_group 1;" ::: "memory");
        } else {
            asm volatile("cp.async.wait_group 0;" ::: "memory");
        }
        __syncthreads();

        const uint32_t bufb = sbase + (uint32_t)(c & 1) * (128 * 128);
        #pragma unroll
        for (int ks = 0; ks < 4; ks++) {
            uint32_t a[2][4];
            #pragma unroll
            for (int mtl = 0; mtl < 2; mtl++) {
                int mt   = wm * 2 + mtl;
                int row  = mt * 16 + (lane & 15);
                int unit = 2 * ks + (lane >> 4);
                uint32_t addr = bufb + row * 128 + ((unit ^ (row & 7)) * 16);
                ldmatrix_x4(a[mtl], addr);
            }
            #pragma unroll
            for (int p = 0; p < 4; p++) {   // 4 n-tile pairs per warp
                uint4 bv = wtf4[(((c * 4 + ks) * 8) + wn * 4 + p) * 32 + lane];
                mma_f16(acc[0][2 * p + 0], a[0], bv.x, bv.y);
                mma_f16(acc[1][2 * p + 0], a[1], bv.x, bv.y);
                mma_f16(acc[0][2 * p + 1], a[0], bv.z, bv.w);
                mma_f16(acc[1][2 * p + 1], a[1], bv.z, bv.w);
            }
        }
        __syncthreads();
    }

    // ---- epilogue ----
    const int g   = lane >> 2;
    const int tig = lane & 3;
    #pragma unroll
    for (int mtl = 0; mtl < 2; mtl++) {
        #pragma unroll
        for (int h = 0; h < 2; h++) {
            int row = m0 + wm * 32 + mtl * 16 + h * 8 + g;
            if (row >= NN) continue;
            #pragma unroll
            for (int ntl = 0; ntl < 8; ntl++) {
                int col = wn * 64 + ntl * 8 + tig * 2;
                float ox = acc[mtl][ntl][h * 2 + 0] + __ldg(&bias[col + 0]);
                float oy = acc[mtl][ntl][h * 2 + 1] + __ldg(&bias[col + 1]);
                if (!LAST) {
                    ox = fmaxf(ox, 0.f); oy = fmaxf(oy, 0.f);
                    __half2 hh = __floats2half2_rn(ox, oy);
                    *(__half2*)&g_hh[(size_t)row * 128 + col] = hh;
                } else {
                    *(float2*)&out[(size_t)row * 128 + col] = make_float2(ox, oy);
                }
            }
        }
    }
}

// ---------------- launch ------------------------------------------------------
extern "C" void kernel_launch(void* const* d_in, const int* in_sizes, int n_in,
                              void* d_out, int out_size) {
    const float* x       = (const float*)d_in[0];
    const int*   ei      = (const int*)d_in[1];
    const float* w_rel1  = (const float*)d_in[2];
    const float* w_root1 = (const float*)d_in[3];
    const float* b1      = (const float*)d_in[4];
    const float* w_rel2  = (const float*)d_in[5];
    const float* w_root2 = (const float*)d_in[6];
    const float* b2      = (const float*)d_in[7];
    const float* w_rel3  = (const float*)d_in[8];
    const float* w_root3 = (const float*)d_in[9];
    const float* b3      = (const float*)d_in[10];
    float*       out     = (float*)d_out;

    const int EB4 = (NE / 4 + 255) / 256;       // 1563
    const int AB  = ((NN * 32) + 255) / 256;
    const int GB  = (NN + 127) / 128;           // 782
    const int CB  = (NN * D / 4 + 255) / 256;   // 12500

    cvt_x_kernel<<<CB, 256>>>(x);               // fp16 copy + cursor zero
    hist_kernel<<<EB4, 256>>>(ei);
    scan1_kernel<<<SCAN_BLOCKS, 1024>>>();
    scan23_kernel<<<SCAN_BLOCKS, 1024>>>();
    fill_kernel<<<EB4, 256>>>(ei);

    // layer 1
    agg_kernel<<<AB, 256>>>();
    prep_wt_kernel<<<192, 256>>>(w_rel1, w_root1, w_rel2, w_root2, w_rel3, w_root3);
    gemm_mma_kernel<false><<<GB, 256>>>(0, b1, nullptr);
    // layer 2
    agg_kernel<<<AB, 256>>>();
    gemm_mma_kernel<false><<<GB, 256>>>(1, b2, nullptr);
    // layer 3 (no relu) -> d_out
    agg_kernel<<<AB, 256>>>();
    gemm_mma_kernel<true><<<GB, 256>>>(2, b3, out);
}